// round 5
// baseline (speedup 1.0000x reference)
#include <cuda_runtime.h>
#include <math.h>
#include <stdint.h>

#define MAXN 20000
#define MAXE 320000

// ---------------- device scratch (no allocs allowed) ----------------
__device__ int   g_is64;
__device__ int   g_src[MAXE];
__device__ int   g_dst[MAXE];
__device__ int   g_esrc[MAXE];
__device__ float g_ewn[MAXE];
__device__ float g_deg[MAXN];
__device__ float g_dinv[MAXN];
__device__ int   g_cnt[MAXN];
__device__ int   g_rowptr[MAXN + 1];
__device__ int   g_cursor[MAXN];
__device__ int   g_part[32];
__device__ int   g_off2[32];
__device__ int   g_total;
__device__ float g_Phc[MAXN * 256];               // [P_h | P_c]
__device__ float g_base[(long long)MAXN * 512];   // permuted gate layout
__device__ float g_h[MAXN * 128];
__device__ float g_c[MAXN * 128];
__device__ float g_z[MAXN * 128];

// ---------------- f32x2 helpers ----------------
#define FMA2(a, x, w) asm("fma.rn.f32x2 %0, %1, %2, %0;" : "+l"(a) : "l"(x), "l"(w))

__device__ __forceinline__ unsigned long long pk2(float v) {
    unsigned long long r;
    asm("mov.b64 %0, {%1, %1};" : "=l"(r) : "f"(v));
    return r;
}
__device__ __forceinline__ void upk2(float& lo, float& hi, unsigned long long v) {
    asm("mov.b64 {%0, %1}, %2;" : "=f"(lo), "=f"(hi) : "l"(v));
}
__device__ __forceinline__ float tanhA(float x) {
    float r; asm("tanh.approx.f32 %0, %1;" : "=f"(r) : "f"(x)); return r;
}
__device__ __forceinline__ float sigA(float x) {
    return fmaf(tanhA(0.5f * x), 0.5f, 0.5f);
}

// ---------------- setup kernels ----------------
__global__ void k_init(int n) {
    int i = blockIdx.x * blockDim.x + threadIdx.x;
    if (i < n) { g_deg[i] = 0.f; g_cnt[i] = 0; }
    if (i == 0) g_is64 = 1;
}

// int64 values < 2^31 have zero high words; int32 edge data has random values.
__global__ void k_detect(const unsigned int* __restrict__ w) {
    unsigned int v = w[2 * threadIdx.x + 1];
    if (v != 0u) g_is64 = 0;
}

__global__ void k_build(const void* __restrict__ ei, const float* __restrict__ ea, int E) {
    int e = blockIdx.x * blockDim.x + threadIdx.x;
    if (e >= E) return;
    int s, d;
    if (g_is64) {
        const long long* p = (const long long*)ei;
        s = (int)p[e]; d = (int)p[E + e];
    } else {
        const int* p = (const int*)ei;
        s = p[e]; d = p[E + e];
    }
    g_src[e] = s; g_dst[e] = d;
    atomicAdd(&g_deg[d], ea[e]);
    atomicAdd(&g_cnt[d], 1);
}

// hierarchical scan pass 1 (+ dinv fused)
__global__ void k_scan1(int n) {
    __shared__ int s[1024];
    int i = blockIdx.x * 1024 + threadIdx.x;
    if (i < n) g_dinv[i] = rsqrtf(g_deg[i] + 1.0f);
    int v = (i < n) ? g_cnt[i] : 0;
    s[threadIdx.x] = v;
    __syncthreads();
    for (int off = 1; off < 1024; off <<= 1) {
        int t = (threadIdx.x >= off) ? s[threadIdx.x - off] : 0;
        __syncthreads();
        s[threadIdx.x] += t;
        __syncthreads();
    }
    if (i < n) g_rowptr[i] = s[threadIdx.x] - v;   // local exclusive
    if (threadIdx.x == 1023) g_part[blockIdx.x] = s[1023];
}

__global__ void k_scan2(int nb) {
    int tid = threadIdx.x;                 // 32 threads
    int v = (tid < nb) ? g_part[tid] : 0;
    int incl = v;
    for (int o = 1; o < 32; o <<= 1) {
        int t = __shfl_up_sync(0xffffffffu, incl, o);
        if (tid >= o) incl += t;
    }
    if (tid < nb) g_off2[tid] = incl - v;
    if (tid == 31) g_total = incl;
}

__global__ void k_scan3(int n) {
    int i = blockIdx.x * 1024 + threadIdx.x;
    if (i < n) {
        int val = g_rowptr[i] + g_off2[blockIdx.x];
        g_rowptr[i] = val;
        g_cursor[i] = val;
    }
    if (i == 0) g_rowptr[n] = g_total;
}

__global__ void k_scatter(const float* __restrict__ ea, int E) {
    int e = blockIdx.x * blockDim.x + threadIdx.x;
    if (e >= E) return;
    int s = g_src[e], d = g_dst[e];
    int pos = atomicAdd(&g_cursor[d], 1);
    g_esrc[pos] = s;
    g_ewn[pos] = g_dinv[s] * ea[e] * g_dinv[d];
}

// ---------------- sparse propagate: one warp per node, 4 floats/lane ----------------
__global__ void k_prop(const float* __restrict__ x, int ldx,
                       float* __restrict__ out, int ldo, int n) {
    int v = (blockIdx.x * blockDim.x + threadIdx.x) >> 5;
    int lane = threadIdx.x & 31;
    if (v >= n) return;
    int beg = g_rowptr[v], end = g_rowptr[v + 1];
    float ax = 0.f, ay = 0.f, az = 0.f, aw = 0.f;
    int e = beg;
    for (; e + 1 < end; e += 2) {
        int s0 = g_esrc[e], s1 = g_esrc[e + 1];
        float w0 = g_ewn[e], w1 = g_ewn[e + 1];
        float4 v0 = __ldg((const float4*)(x + (long long)s0 * ldx) + lane);
        float4 v1 = __ldg((const float4*)(x + (long long)s1 * ldx) + lane);
        ax = fmaf(w0, v0.x, ax); ay = fmaf(w0, v0.y, ay);
        az = fmaf(w0, v0.z, az); aw = fmaf(w0, v0.w, aw);
        ax = fmaf(w1, v1.x, ax); ay = fmaf(w1, v1.y, ay);
        az = fmaf(w1, v1.z, az); aw = fmaf(w1, v1.w, aw);
    }
    if (e < end) {
        int s0 = g_esrc[e];
        float w0 = g_ewn[e];
        float4 v0 = __ldg((const float4*)(x + (long long)s0 * ldx) + lane);
        ax = fmaf(w0, v0.x, ax); ay = fmaf(w0, v0.y, ay);
        az = fmaf(w0, v0.z, az); aw = fmaf(w0, v0.w, aw);
    }
    float di = g_dinv[v];
    float w2 = di * di;
    float4 vv = __ldg((const float4*)(x + (long long)v * ldx) + lane);
    ax = fmaf(w2, vv.x, ax); ay = fmaf(w2, vv.y, ay);
    az = fmaf(w2, vv.z, az); aw = fmaf(w2, vv.w, aw);
    float4 o; o.x = ax; o.y = ay; o.z = az; o.w = aw;
    *((float4*)(out + (long long)v * ldo) + lane) = o;
}

// ---------------- init GEMM: states = elu(Phc[N,256] @ W_init[256,256] + b_init)
__global__ void __launch_bounds__(128, 3) k_gemm_init(const float* __restrict__ W,
                                                      const float* __restrict__ b, int n) {
    __shared__ float ws[16][256];
    __shared__ unsigned long long xs2[32][17];
    const int tid = threadIdx.x;
    const int tx = tid & 31;
    const int ty = tid >> 5;
    const int row0 = blockIdx.x * 32;

    unsigned long long acc[8][4];
#pragma unroll
    for (int i = 0; i < 8; i++)
#pragma unroll
        for (int q = 0; q < 4; q++) acc[i][q] = 0ull;

    for (int k0 = 0; k0 < 256; k0 += 16) {
#pragma unroll
        for (int it = 0; it < 8; it++) {
            int idx = tid + it * 128;
            int r = idx >> 6, c4 = idx & 63;
            float4 v = __ldg((const float4*)(W + (long long)(k0 + r) * 256) + c4);
            *(float4*)&ws[r][c4 * 4] = v;
        }
        {
            int r = tid >> 2, kk = (tid & 3) * 4;
            int gr = row0 + r;
            float4 v = make_float4(0.f, 0.f, 0.f, 0.f);
            if (gr < n) v = __ldg((const float4*)(g_Phc + (long long)gr * 256 + k0 + kk));
            xs2[r][kk + 0] = pk2(v.x); xs2[r][kk + 1] = pk2(v.y);
            xs2[r][kk + 2] = pk2(v.z); xs2[r][kk + 3] = pk2(v.w);
        }
        __syncthreads();
#pragma unroll
        for (int k = 0; k < 16; k++) {
            unsigned long long w2[4];
#pragma unroll
            for (int q = 0; q < 2; q++) {
                const unsigned long long* wp =
                    (const unsigned long long*)&ws[k][q * 128 + tx * 4];
                w2[2 * q] = wp[0]; w2[2 * q + 1] = wp[1];
            }
#pragma unroll
            for (int i = 0; i < 8; i++) {
                unsigned long long xx = xs2[ty + 4 * i][k];
#pragma unroll
                for (int q = 0; q < 4; q++) FMA2(acc[i][q], xx, w2[q]);
            }
        }
        __syncthreads();
    }

    float4 b0 = *(const float4*)&b[0 * 128 + 4 * tx];
    float4 b1 = *(const float4*)&b[1 * 128 + 4 * tx];
#pragma unroll
    for (int i = 0; i < 8; i++) {
        int r = row0 + ty + 4 * i;
        if (r >= n) continue;
        float v[8];
        upk2(v[0], v[1], acc[i][0]); upk2(v[2], v[3], acc[i][1]);
        upk2(v[4], v[5], acc[i][2]); upk2(v[6], v[7], acc[i][3]);
        v[0] += b0.x; v[1] += b0.y; v[2] += b0.z; v[3] += b0.w;
        v[4] += b1.x; v[5] += b1.y; v[6] += b1.z; v[7] += b1.w;
#pragma unroll
        for (int m = 0; m < 8; m++) v[m] = (v[m] > 0.f) ? v[m] : expm1f(v[m]);
        float4 oh; oh.x = v[0]; oh.y = v[1]; oh.z = v[2]; oh.w = v[3];
        float4 oc; oc.x = v[4]; oc.y = v[5]; oc.z = v[6]; oc.w = v[7];
        *(float4*)&g_h[(long long)r * 128 + 4 * tx] = oh;
        *(float4*)&g_c[(long long)r * 128 + 4 * tx] = oc;
    }
}

// ---------------- main GEMM, half-width tiles for tail packing ----------------
// grid (mtiles, 2): CTA computes rows [row0,row0+32) x 256 permuted cols for half t.
// Permuted col p (within half): p = g*64 + j, g=gate(0..3), j=hcol-in-half(0..63);
// orig W col = g*128 + t*64 + j; h-col = t*64 + j.
// Thread tx holds cols q2*128 + tx*4 + {0..3} for q2=0,1:
//   tx<16 : gates (i, o) of hcols tx*4..tx*4+3
//   tx>=16: gates (f, g) of hcols (tx-16)*4..+3   -> pair via shfl.xor 16
// mode 0: o512[r*512 + t*256 + p] = D + bc[orig col]  (permuted base)
// mode 1: gates = D + base_perm; LSTM update; write g_h/g_c/oseq
__global__ void __launch_bounds__(128, 5)
k_g256(const float* __restrict__ X, int ldx, const float* __restrict__ W, int K,
       const float* __restrict__ aux, float* __restrict__ o512,
       float* __restrict__ oseq, int n, int mode) {
    __shared__ float ws[16][256];
    __shared__ unsigned long long xs2[32][17];
    const int tid = threadIdx.x;
    const int tx = tid & 31;
    const int ty = tid >> 5;
    const int row0 = blockIdx.x * 32;
    const int t = blockIdx.y;

    unsigned long long acc[8][4];
#pragma unroll
    for (int i = 0; i < 8; i++)
#pragma unroll
        for (int q = 0; q < 4; q++) acc[i][q] = 0ull;

    for (int k0 = 0; k0 < K; k0 += 16) {
        // stage W slab with gate permutation: ws[r][p] = W[(k0+r)*512 + orig(p)]
#pragma unroll
        for (int it = 0; it < 8; it++) {
            int idx = tid + it * 128;          // 0..1023
            int r = idx >> 6, cc = idx & 63;   // cc*4 = p
            int g = cc >> 4, j = (cc & 15) * 4;
            float4 v = __ldg((const float4*)(W + (long long)(k0 + r) * 512 + g * 128 + t * 64 + j));
            *(float4*)&ws[r][cc * 4] = v;
        }
        {
            int r = tid >> 2, kk = (tid & 3) * 4;
            int gr = row0 + r;
            float4 v = make_float4(0.f, 0.f, 0.f, 0.f);
            if (gr < n) v = __ldg((const float4*)(X + (long long)gr * ldx + k0 + kk));
            xs2[r][kk + 0] = pk2(v.x); xs2[r][kk + 1] = pk2(v.y);
            xs2[r][kk + 2] = pk2(v.z); xs2[r][kk + 3] = pk2(v.w);
        }
        __syncthreads();
#pragma unroll
        for (int k = 0; k < 16; k++) {
            unsigned long long w2[4];
#pragma unroll
            for (int q2 = 0; q2 < 2; q2++) {
                const unsigned long long* wp =
                    (const unsigned long long*)&ws[k][q2 * 128 + tx * 4];
                w2[2 * q2] = wp[0]; w2[2 * q2 + 1] = wp[1];
            }
#pragma unroll
            for (int i = 0; i < 8; i++) {
                unsigned long long xx = xs2[ty + 4 * i][k];
#pragma unroll
                for (int q = 0; q < 4; q++) FMA2(acc[i][q], xx, w2[q]);
            }
        }
        __syncthreads();
    }

    if (mode == 0) {
        // bias for this thread's cols: gate g0 = q2*2? no: gate = q2*2 + (tx>>4)? cols:
        // q2=0 -> gate (tx>>4) in {0:i,1:f}; q2=1 -> gate 2+(tx>>4) in {o,g}
        int gsel = tx >> 4;
        int j0 = (tx & 15) * 4;
        float4 b0 = *(const float4*)&aux[(0 * 2 + gsel) * 128 + t * 64 + j0];
        float4 b1 = *(const float4*)&aux[(2 + gsel) * 128 + t * 64 + j0];
#pragma unroll
        for (int i = 0; i < 8; i++) {
            int r = row0 + ty + 4 * i;
            if (r >= n) continue;
            float v[8];
            upk2(v[0], v[1], acc[i][0]); upk2(v[2], v[3], acc[i][1]);
            upk2(v[4], v[5], acc[i][2]); upk2(v[6], v[7], acc[i][3]);
            float4 o0, o1;
            o0.x = v[0] + b0.x; o0.y = v[1] + b0.y; o0.z = v[2] + b0.z; o0.w = v[3] + b0.w;
            o1.x = v[4] + b1.x; o1.y = v[5] + b1.y; o1.z = v[6] + b1.z; o1.w = v[7] + b1.w;
            float* orow = o512 + (long long)r * 512 + t * 256 + tx * 4;
            *(float4*)&orow[0]   = o0;
            *(float4*)&orow[128] = o1;
        }
    } else {
#pragma unroll
        for (int i = 0; i < 8; i++) {
            int r = row0 + ty + 4 * i;
            // whole warp shares r -> uniform guard ok around shfls
            if (r >= n) continue;
            float a[4], b[4];
            upk2(a[0], a[1], acc[i][0]); upk2(a[2], a[3], acc[i][1]);
            upk2(b[0], b[1], acc[i][2]); upk2(b[2], b[3], acc[i][3]);
            const float* brow = aux + (long long)r * 512 + t * 256 + tx * 4;
            float4 ba = *(const float4*)&brow[0];
            float4 bb = *(const float4*)&brow[128];
            a[0] += ba.x; a[1] += ba.y; a[2] += ba.z; a[3] += ba.w;
            b[0] += bb.x; b[1] += bb.y; b[2] += bb.z; b[3] += bb.w;
            float ra[4], rb[4];
#pragma unroll
            for (int m = 0; m < 4; m++) {
                ra[m] = __shfl_xor_sync(0xffffffffu, a[m], 16);
                rb[m] = __shfl_xor_sync(0xffffffffu, b[m], 16);
            }
            if (tx < 16) {
                // this lane: a=i, b=o; partner: ra=f, rb=g
                long long ix = (long long)r * 128 + t * 64 + tx * 4;
                float4 cold = *(const float4*)&g_c[ix];
                float co[4] = {cold.x, cold.y, cold.z, cold.w};
                float cn[4], hn[4];
#pragma unroll
                for (int m = 0; m < 4; m++) {
                    cn[m] = sigA(ra[m]) * co[m] + sigA(a[m]) * tanhA(rb[m]);
                    hn[m] = sigA(b[m]) * tanhA(cn[m]);
                }
                float4 oc; oc.x = cn[0]; oc.y = cn[1]; oc.z = cn[2]; oc.w = cn[3];
                float4 oh; oh.x = hn[0]; oh.y = hn[1]; oh.z = hn[2]; oh.w = hn[3];
                *(float4*)&g_c[ix] = oc;
                *(float4*)&g_h[ix] = oh;
                *(float4*)&oseq[ix] = oh;
            }
        }
    }
}

// ---------------- host launcher ----------------
extern "C" void kernel_launch(void* const* d_in, const int* in_sizes, int n_in,
                              void* d_out, int out_size) {
    const float* h  = (const float*)d_in[0];
    const float* c  = (const float*)d_in[1];
    const void*  ei = d_in[2];
    const float* ea = (const float*)d_in[3];
    const float* Wi = (const float*)d_in[4];
    const float* bi = (const float*)d_in[5];
    const float* Wc = (const float*)d_in[6];
    const float* bc = (const float*)d_in[7];
    float* out = (float*)d_out;

    int n   = in_sizes[0] / 128;
    int E   = in_sizes[3];
    int seq = out_size / (n * 128);

    static float* p_Phc = nullptr;
    static float* p_base = nullptr;
    static float* p_h = nullptr;
    static float* p_z = nullptr;
    if (!p_Phc) {
        cudaGetSymbolAddress((void**)&p_Phc, g_Phc);
        cudaGetSymbolAddress((void**)&p_base, g_base);
        cudaGetSymbolAddress((void**)&p_h, g_h);
        cudaGetSymbolAddress((void**)&p_z, g_z);
    }

    int nb256 = (n + 255) / 256;
    int eb256 = (E + 255) / 256;
    int nb1024 = (n + 1023) / 1024;
    int mtiles = (n + 31) / 32;
    int prop_blocks = (n * 32 + 255) / 256;
    dim3 gemm_grid(mtiles, 2);

    // ---- graph setup (per launch; deterministic) ----
    k_init<<<nb256, 256>>>(n);
    k_detect<<<1, 128>>>((const unsigned int*)ei);
    k_build<<<eb256, 256>>>(ei, ea, E);
    k_scan1<<<nb1024, 1024>>>(n);        // also computes dinv
    k_scan2<<<1, 32>>>(nb1024);
    k_scan3<<<nb1024, 1024>>>(n);
    k_scatter<<<eb256, 256>>>(ea, E);

    // ---- loop-invariant precompute ----
    k_prop<<<prop_blocks, 256>>>(h, 128, p_Phc, 256, n);        // P_h
    k_prop<<<prop_blocks, 256>>>(c, 128, p_Phc + 128, 256, n);  // P_c
    k_gemm_init<<<(n + 31) / 32, 128>>>(Wi, bi, n);             // -> g_h, g_c
    // base_perm = P_h @ Wc[0:128] + b_cell
    k_g256<<<gemm_grid, 128>>>(p_Phc, 256, Wc, 128, bc, p_base, nullptr, n, 0);

    // ---- sequence ----
    for (int tt = 0; tt < seq; tt++) {
        k_prop<<<prop_blocks, 256>>>(p_h, 128, p_z, 128, n);
        k_g256<<<gemm_grid, 128>>>(p_z, 128, Wc + (long long)128 * 512, 128,
                                   p_base, nullptr, out + (long long)tt * n * 128, n, 1);
    }
}

// round 6
// speedup vs baseline: 1.1759x; 1.1759x over previous
#include <cuda_runtime.h>
#include <cuda_bf16.h>
#include <math.h>
#include <stdint.h>

#define MAXN 20000
#define MAXE 320000

// ---------------- device scratch (no allocs allowed) ----------------
__device__ int   g_is64;
__device__ int   g_src[MAXE];
__device__ int   g_dst[MAXE];
__device__ int   g_esrc[MAXE];
__device__ float g_ewn[MAXE];
__device__ float g_deg[MAXN];
__device__ float g_dinv[MAXN];
__device__ int   g_cnt[MAXN];
__device__ int   g_rowptr[MAXN + 1];
__device__ int   g_cursor[MAXN];
__device__ int   g_part[32];
__device__ int   g_off2[32];
__device__ int   g_total;
__device__ float g_Phc[MAXN * 256];               // [P_h | P_c]
__device__ float g_base[(long long)MAXN * 512];   // permuted gate layout
__device__ float g_h[MAXN * 128];
__device__ float g_c[MAXN * 128];
__device__ float g_z[MAXN * 128];
// bf16-split transposed weights
// W_cell: [m in {0,1}][p = permuted col 0..511][k 0..127], perm p = t*128 + j*4 + q
__device__ __nv_bfloat16 g_WTh[2 * 512 * 128];
__device__ __nv_bfloat16 g_WTl[2 * 512 * 128];
// W_init: [p 0..255][k 0..255]
__device__ __nv_bfloat16 g_WIh[256 * 256];
__device__ __nv_bfloat16 g_WIl[256 * 256];

// ---------------- helpers ----------------
__device__ __forceinline__ float tanhA(float x) {
    float r; asm("tanh.approx.f32 %0, %1;" : "=f"(r) : "f"(x)); return r;
}
__device__ __forceinline__ float sigA(float x) {
    return fmaf(tanhA(0.5f * x), 0.5f, 0.5f);
}
__device__ __forceinline__ uint32_t smem_u32(const void* p) {
    uint32_t a;
    asm("{ .reg .u64 t; cvta.to.shared.u64 t, %1; cvt.u32.u64 %0, t; }" : "=r"(a) : "l"(p));
    return a;
}

#define LDSM4(r0, r1, r2, r3, a) \
    asm volatile("ldmatrix.sync.aligned.m8n8.x4.shared.b16 {%0,%1,%2,%3}, [%4];" \
        : "=r"(r0), "=r"(r1), "=r"(r2), "=r"(r3) : "r"(a))

#define MMA16816(d, a0, a1, a2, a3, b0, b1) \
    asm volatile("mma.sync.aligned.m16n8k16.row.col.f32.bf16.bf16.f32 " \
        "{%0,%1,%2,%3}, {%4,%5,%6,%7}, {%8,%9}, {%0,%1,%2,%3};" \
        : "+f"((d)[0]), "+f"((d)[1]), "+f"((d)[2]), "+f"((d)[3]) \
        : "r"(a0), "r"(a1), "r"(a2), "r"(a3), "r"(b0), "r"(b1))

__device__ __forceinline__ void split8(const float* v, uint4& hv, uint4& lv) {
    unsigned short* hp = (unsigned short*)&hv;
    unsigned short* lp = (unsigned short*)&lv;
#pragma unroll
    for (int i = 0; i < 8; i++) {
        __nv_bfloat16 hb = __float2bfloat16_rn(v[i]);
        float lf = v[i] - __bfloat162float(hb);
        __nv_bfloat16 lb = __float2bfloat16_rn(lf);
        hp[i] = *(unsigned short*)&hb;
        lp[i] = *(unsigned short*)&lb;
    }
}

// ---------------- setup kernels ----------------
__global__ void k_init(int n) {
    int i = blockIdx.x * blockDim.x + threadIdx.x;
    if (i < n) { g_deg[i] = 0.f; g_cnt[i] = 0; }
    if (i == 0) g_is64 = 1;
}

__global__ void k_detect(const unsigned int* __restrict__ w) {
    unsigned int v = w[2 * threadIdx.x + 1];
    if (v != 0u) g_is64 = 0;
}

__global__ void k_build(const void* __restrict__ ei, const float* __restrict__ ea, int E) {
    int e = blockIdx.x * blockDim.x + threadIdx.x;
    if (e >= E) return;
    int s, d;
    if (g_is64) {
        const long long* p = (const long long*)ei;
        s = (int)p[e]; d = (int)p[E + e];
    } else {
        const int* p = (const int*)ei;
        s = p[e]; d = p[E + e];
    }
    g_src[e] = s; g_dst[e] = d;
    atomicAdd(&g_deg[d], ea[e]);
    atomicAdd(&g_cnt[d], 1);
}

// hierarchical scan pass 1 (+ dinv fused)
__global__ void k_scan1(int n) {
    __shared__ int s[1024];
    int i = blockIdx.x * 1024 + threadIdx.x;
    if (i < n) g_dinv[i] = rsqrtf(g_deg[i] + 1.0f);
    int v = (i < n) ? g_cnt[i] : 0;
    s[threadIdx.x] = v;
    __syncthreads();
    for (int off = 1; off < 1024; off <<= 1) {
        int t = (threadIdx.x >= off) ? s[threadIdx.x - off] : 0;
        __syncthreads();
        s[threadIdx.x] += t;
        __syncthreads();
    }
    if (i < n) g_rowptr[i] = s[threadIdx.x] - v;   // local exclusive
    if (threadIdx.x == 1023) g_part[blockIdx.x] = s[1023];
}

__global__ void k_scan2(int nb) {
    int tid = threadIdx.x;                 // 32 threads
    int v = (tid < nb) ? g_part[tid] : 0;
    int incl = v;
    for (int o = 1; o < 32; o <<= 1) {
        int t = __shfl_up_sync(0xffffffffu, incl, o);
        if (tid >= o) incl += t;
    }
    if (tid < nb) g_off2[tid] = incl - v;
    if (tid == 31) g_total = incl;
}

__global__ void k_scan3(int n) {
    int i = blockIdx.x * 1024 + threadIdx.x;
    if (i < n) {
        int val = g_rowptr[i] + g_off2[blockIdx.x];
        g_rowptr[i] = val;
        g_cursor[i] = val;
    }
    if (i == 0) g_rowptr[n] = g_total;
}

__global__ void k_scatter(const float* __restrict__ ea, int E) {
    int e = blockIdx.x * blockDim.x + threadIdx.x;
    if (e >= E) return;
    int s = g_src[e], d = g_dst[e];
    int pos = atomicAdd(&g_cursor[d], 1);
    g_esrc[pos] = s;
    g_ewn[pos] = g_dinv[s] * ea[e] * g_dinv[d];
}

// W_cell transpose + gate-interleave permute + bf16 split
// permuted p = t*128 + j*4 + q  <->  orig col q*128 + t*32 + j
__global__ void k_splitW(const float* __restrict__ Wc) {
    int id = blockIdx.x * blockDim.x + threadIdx.x;   // 0 .. 131071
    int m = id >> 16;
    int rem = id & 65535;
    int p = rem >> 7;
    int k = rem & 127;
    int t = p >> 7, r7 = p & 127;
    int j = r7 >> 2, q = r7 & 3;
    int nc = q * 128 + t * 32 + j;
    float v = Wc[(long long)(m * 128 + k) * 512 + nc];
    __nv_bfloat16 hb = __float2bfloat16_rn(v);
    float lf = v - __bfloat162float(hb);
    g_WTh[id] = hb;
    g_WTl[id] = __float2bfloat16_rn(lf);
}

// W_init transpose + bf16 split: [p][k] = Wi[k][p]
__global__ void k_splitWi(const float* __restrict__ Wi) {
    int id = blockIdx.x * blockDim.x + threadIdx.x;   // 0 .. 65535
    int p = id >> 8;
    int k = id & 255;
    float v = Wi[(long long)k * 256 + p];
    __nv_bfloat16 hb = __float2bfloat16_rn(v);
    float lf = v - __bfloat162float(hb);
    g_WIh[id] = hb;
    g_WIl[id] = __float2bfloat16_rn(lf);
}

// ---------------- sparse propagate ----------------
__global__ void k_prop(const float* __restrict__ x, int ldx,
                       float* __restrict__ out, int ldo, int n) {
    int v = (blockIdx.x * blockDim.x + threadIdx.x) >> 5;
    int lane = threadIdx.x & 31;
    if (v >= n) return;
    int beg = g_rowptr[v], end = g_rowptr[v + 1];
    float ax = 0.f, ay = 0.f, az = 0.f, aw = 0.f;
    int e = beg;
    for (; e + 1 < end; e += 2) {
        int s0 = g_esrc[e], s1 = g_esrc[e + 1];
        float w0 = g_ewn[e], w1 = g_ewn[e + 1];
        float4 v0 = __ldg((const float4*)(x + (long long)s0 * ldx) + lane);
        float4 v1 = __ldg((const float4*)(x + (long long)s1 * ldx) + lane);
        ax = fmaf(w0, v0.x, ax); ay = fmaf(w0, v0.y, ay);
        az = fmaf(w0, v0.z, az); aw = fmaf(w0, v0.w, aw);
        ax = fmaf(w1, v1.x, ax); ay = fmaf(w1, v1.y, ay);
        az = fmaf(w1, v1.z, az); aw = fmaf(w1, v1.w, aw);
    }
    if (e < end) {
        int s0 = g_esrc[e];
        float w0 = g_ewn[e];
        float4 v0 = __ldg((const float4*)(x + (long long)s0 * ldx) + lane);
        ax = fmaf(w0, v0.x, ax); ay = fmaf(w0, v0.y, ay);
        az = fmaf(w0, v0.z, az); aw = fmaf(w0, v0.w, aw);
    }
    float di = g_dinv[v];
    float w2 = di * di;
    float4 vv = __ldg((const float4*)(x + (long long)v * ldx) + lane);
    ax = fmaf(w2, vv.x, ax); ay = fmaf(w2, vv.y, ay);
    az = fmaf(w2, vv.z, az); aw = fmaf(w2, vv.w, aw);
    float4 o; o.x = ax; o.y = ay; o.z = az; o.w = aw;
    *((float4*)(out + (long long)v * ldo) + lane) = o;
}

// ---------------- staging: one 32-wide K slab into smem buffer ----------------
// buffer layout (per 40960B buf): Ahi[0,10240) Alo[+10240) Bhi[+20480) Blo[+30720)
// rows 80B (32 bf16 = 4 granules of 16B at g*16): bank-rotated by stride 5 granules.
__device__ __forceinline__ void stage_slab(
    char* sm, uint32_t bufoff, const float* __restrict__ X, int ldx,
    const __nv_bfloat16* __restrict__ Bh, const __nv_bfloat16* __restrict__ Bl,
    int K, int n, int m0, int nbase, int tid, int ks) {
    float4 pa[2][2];
    uint4 pbh[2], pbl[2];
#pragma unroll
    for (int it = 0; it < 2; it++) {
        int gid = it * 256 + tid;        // 0..511
        int row = gid >> 2, g = gid & 3;
        int grow = m0 + row;
        if (grow < n) {
            const float4* xp = (const float4*)(X + (size_t)grow * ldx + ks * 32 + g * 8);
            pa[it][0] = __ldg(xp);
            pa[it][1] = __ldg(xp + 1);
        } else {
            pa[it][0] = make_float4(0.f, 0.f, 0.f, 0.f);
            pa[it][1] = make_float4(0.f, 0.f, 0.f, 0.f);
        }
        size_t src = (size_t)(nbase + row) * K + ks * 32 + g * 8;
        pbh[it] = __ldg((const uint4*)(Bh + src));
        pbl[it] = __ldg((const uint4*)(Bl + src));
    }
#pragma unroll
    for (int it = 0; it < 2; it++) {
        int gid = it * 256 + tid;
        int row = gid >> 2, g = gid & 3;
        uint32_t off = bufoff + row * 80 + g * 16;
        uint4 hv, lv;
        split8((const float*)&pa[it][0], hv, lv);
        *(uint4*)(sm + off) = hv;
        *(uint4*)(sm + 10240 + off) = lv;
        *(uint4*)(sm + 20480 + off) = pbh[it];
        *(uint4*)(sm + 30720 + off) = pbl[it];
    }
}

// ---------------- pipelined tensor-core GEMM (mma.sync bf16 split-3) ----------------
// C[128 x 128] = X[m0:m0+128, :K] @ B[n0:n0+128, :K]^T, B row-major [P][K] bf16 hi/lo.
// mode 0: o512[r*512 + t*128 + c] = D + bc[orig col]   (permuted base precompute)
// mode 1: LSTM gates: D + base; update g_h/g_c; write oseq
// mode 2: init: elu(D + bi[col]) -> g_h (cols<128) / g_c
__global__ void __launch_bounds__(256, 2)
k_mma(const float* __restrict__ X, int ldx,
      const __nv_bfloat16* __restrict__ Bh, const __nv_bfloat16* __restrict__ Bl,
      int K, const float* __restrict__ aux, float* __restrict__ o512,
      float* __restrict__ oseq, int n, int mode) {
    extern __shared__ char sm[];
    const uint32_t sb = smem_u32(sm);
    const int tid = threadIdx.x;
    const int lane = tid & 31;
    const int wid = tid >> 5;
    const int m0 = blockIdx.x * 128;
    const int t = blockIdx.y;
    const int mw = (wid & 3) * 32;
    const int nw = (wid >> 2) * 64;

    float acc[2][8][4];
#pragma unroll
    for (int i = 0; i < 2; i++)
#pragma unroll
        for (int j = 0; j < 8; j++)
#pragma unroll
            for (int q = 0; q < 4; q++) acc[i][j][q] = 0.f;

    const int nslab = K >> 5;
    for (int ks = 0; ks < nslab; ks++) {
        if (ks == 0) {
            stage_slab(sm, 0, X, ldx, Bh, Bl, K, n, m0, t * 128, tid, 0);
            __syncthreads();
        }
        if (ks + 1 < nslab)
            stage_slab(sm, ((ks + 1) & 1) * 40960, X, ldx, Bh, Bl, K, n, m0, t * 128, tid, ks + 1);
        // ---- compute slab ks from buf[ks&1] ----
        uint32_t abase = sb + (ks & 1) * 40960;
        uint32_t bbase = abase + 20480;
#pragma unroll
        for (int kc = 0; kc < 2; kc++) {
            uint32_t ah[2][4], al[2][4];
#pragma unroll
            for (int mf = 0; mf < 2; mf++) {
                int row = mw + mf * 16 + (lane & 15);
                int g = kc * 2 + (lane >> 4);
                uint32_t a = abase + row * 80 + g * 16;
                LDSM4(ah[mf][0], ah[mf][1], ah[mf][2], ah[mf][3], a);
                LDSM4(al[mf][0], al[mf][1], al[mf][2], al[mf][3], a + 10240);
            }
#pragma unroll
            for (int bp = 0; bp < 4; bp++) {
                int p = nw + bp * 16 + ((lane >> 4) << 3) + (lane & 7);
                int g = kc * 2 + ((lane >> 3) & 1);
                uint32_t a = bbase + p * 80 + g * 16;
                uint32_t h0, h1, h2, h3, l0, l1, l2, l3;
                LDSM4(h0, h1, h2, h3, a);
                LDSM4(l0, l1, l2, l3, a + 10240);
#pragma unroll
                for (int mf = 0; mf < 2; mf++) {
                    MMA16816(acc[mf][2 * bp], ah[mf][0], ah[mf][1], ah[mf][2], ah[mf][3], h0, h1);
                    MMA16816(acc[mf][2 * bp], ah[mf][0], ah[mf][1], ah[mf][2], ah[mf][3], l0, l1);
                    MMA16816(acc[mf][2 * bp], al[mf][0], al[mf][1], al[mf][2], al[mf][3], h0, h1);
                    MMA16816(acc[mf][2 * bp + 1], ah[mf][0], ah[mf][1], ah[mf][2], ah[mf][3], h2, h3);
                    MMA16816(acc[mf][2 * bp + 1], ah[mf][0], ah[mf][1], ah[mf][2], ah[mf][3], l2, l3);
                    MMA16816(acc[mf][2 * bp + 1], al[mf][0], al[mf][1], al[mf][2], al[mf][3], h2, h3);
                }
            }
        }
        __syncthreads();
    }

    // ---- epilogue ----
#pragma unroll
    for (int mf = 0; mf < 2; mf++) {
        int r0 = m0 + mw + mf * 16 + (lane >> 2);
        int r1 = r0 + 8;
#pragma unroll
        for (int nf = 0; nf < 8; nf++) {
            float d0 = acc[mf][nf][0], d1 = acc[mf][nf][1];
            float d2 = acc[mf][nf][2], d3 = acc[mf][nf][3];
            int c0 = nw + nf * 8 + (lane & 3) * 2;
            if (mode == 2) {
                int gc = t * 128 + c0;
                float2 bb = *(const float2*)(aux + gc);
                float* dst = (gc < 128) ? (g_h + gc) : (g_c + gc - 128);
                if (r0 < n) {
                    float e0 = d0 + bb.x, e1 = d1 + bb.y;
                    e0 = (e0 > 0.f) ? e0 : expm1f(e0);
                    e1 = (e1 > 0.f) ? e1 : expm1f(e1);
                    float2 o; o.x = e0; o.y = e1;
                    *(float2*)(dst + (size_t)r0 * 128) = o;
                }
                if (r1 < n) {
                    float e0 = d2 + bb.x, e1 = d3 + bb.y;
                    e0 = (e0 > 0.f) ? e0 : expm1f(e0);
                    e1 = (e1 > 0.f) ? e1 : expm1f(e1);
                    float2 o; o.x = e0; o.y = e1;
                    *(float2*)(dst + (size_t)r1 * 128) = o;
                }
            } else if (mode == 0) {
                int j = c0 >> 2, q = c0 & 3;
                float bb0 = aux[q * 128 + t * 32 + j];
                float bb1 = aux[(q + 1) * 128 + t * 32 + j];
                if (r0 < n) {
                    float2 o; o.x = d0 + bb0; o.y = d1 + bb1;
                    *(float2*)(o512 + (size_t)r0 * 512 + t * 128 + c0) = o;
                }
                if (r1 < n) {
                    float2 o; o.x = d2 + bb0; o.y = d3 + bb1;
                    *(float2*)(o512 + (size_t)r1 * 512 + t * 128 + c0) = o;
                }
            } else {
                float2 b0 = make_float2(0.f, 0.f), b1 = make_float2(0.f, 0.f);
                if (r0 < n) b0 = *(const float2*)(aux + (size_t)r0 * 512 + t * 128 + c0);
                if (r1 < n) b1 = *(const float2*)(aux + (size_t)r1 * 512 + t * 128 + c0);
                float v0 = d0 + b0.x, v1 = d1 + b0.y;
                float v2 = d2 + b1.x, v3 = d3 + b1.y;
                float u0 = __shfl_xor_sync(0xffffffffu, v0, 1);
                float u1 = __shfl_xor_sync(0xffffffffu, v1, 1);
                float u2 = __shfl_xor_sync(0xffffffffu, v2, 1);
                float u3 = __shfl_xor_sync(0xffffffffu, v3, 1);
                if (!(lane & 1)) {
                    // this lane: (i, f); partner: (o, g)
                    int j = c0 >> 2;
                    int hcol = t * 32 + j;
                    if (r0 < n) {
                        size_t ix = (size_t)r0 * 128 + hcol;
                        float cold = g_c[ix];
                        float cn = sigA(v1) * cold + sigA(v0) * tanhA(u1);
                        float hn = sigA(u0) * tanhA(cn);
                        g_c[ix] = cn; g_h[ix] = hn; oseq[ix] = hn;
                    }
                    if (r1 < n) {
                        size_t ix = (size_t)r1 * 128 + hcol;
                        float cold = g_c[ix];
                        float cn = sigA(v3) * cold + sigA(v2) * tanhA(u3);
                        float hn = sigA(u2) * tanhA(cn);
                        g_c[ix] = cn; g_h[ix] = hn; oseq[ix] = hn;
                    }
                }
            }
        }
    }
}

// ---------------- host launcher ----------------
extern "C" void kernel_launch(void* const* d_in, const int* in_sizes, int n_in,
                              void* d_out, int out_size) {
    const float* h  = (const float*)d_in[0];
    const float* c  = (const float*)d_in[1];
    const void*  ei = d_in[2];
    const float* ea = (const float*)d_in[3];
    const float* Wi = (const float*)d_in[4];
    const float* bi = (const float*)d_in[5];
    const float* Wc = (const float*)d_in[6];
    const float* bc = (const float*)d_in[7];
    float* out = (float*)d_out;

    int n   = in_sizes[0] / 128;
    int E   = in_sizes[3];
    int seq = out_size / (n * 128);

    static float* p_Phc = nullptr;
    static float* p_base = nullptr;
    static float* p_h = nullptr;
    static float* p_z = nullptr;
    static __nv_bfloat16* p_WTh = nullptr;
    static __nv_bfloat16* p_WTl = nullptr;
    static __nv_bfloat16* p_WIh = nullptr;
    static __nv_bfloat16* p_WIl = nullptr;
    if (!p_Phc) {
        cudaGetSymbolAddress((void**)&p_Phc, g_Phc);
        cudaGetSymbolAddress((void**)&p_base, g_base);
        cudaGetSymbolAddress((void**)&p_h, g_h);
        cudaGetSymbolAddress((void**)&p_z, g_z);
        cudaGetSymbolAddress((void**)&p_WTh, g_WTh);
        cudaGetSymbolAddress((void**)&p_WTl, g_WTl);
        cudaGetSymbolAddress((void**)&p_WIh, g_WIh);
        cudaGetSymbolAddress((void**)&p_WIl, g_WIl);
        cudaFuncSetAttribute(k_mma, cudaFuncAttributeMaxDynamicSharedMemorySize, 81920);
    }

    int nb256 = (n + 255) / 256;
    int eb256 = (E + 255) / 256;
    int nb1024 = (n + 1023) / 1024;
    int mtiles = (n + 127) / 128;
    int prop_blocks = (n * 32 + 255) / 256;
    size_t smem_sz = 81920;

    // ---- graph setup (per launch; deterministic) ----
    k_init<<<nb256, 256>>>(n);
    k_detect<<<1, 128>>>((const unsigned int*)ei);
    k_build<<<eb256, 256>>>(ei, ea, E);
    k_scan1<<<nb1024, 1024>>>(n);        // also computes dinv
    k_scan2<<<1, 32>>>(nb1024);
    k_scan3<<<nb1024, 1024>>>(n);
    k_scatter<<<eb256, 256>>>(ea, E);
    k_splitW<<<512, 256>>>(Wc);
    k_splitWi<<<256, 256>>>(Wi);

    // ---- loop-invariant precompute ----
    k_prop<<<prop_blocks, 256>>>(h, 128, p_Phc, 256, n);        // P_h
    k_prop<<<prop_blocks, 256>>>(c, 128, p_Phc + 128, 256, n);  // P_c
    // init: elu(Phc @ W_init + b_init) -> g_h, g_c
    k_mma<<<dim3(mtiles, 2), 256, smem_sz>>>(p_Phc, 256, p_WIh, p_WIl, 256,
                                             bi, nullptr, nullptr, n, 2);
    // base_perm = P_h @ Wc[0:128] + b_cell
    k_mma<<<dim3(mtiles, 4), 256, smem_sz>>>(p_Phc, 256, p_WTh, p_WTl, 128,
                                             bc, p_base, nullptr, n, 0);

    // ---- sequence ----
    for (int tt = 0; tt < seq; tt++) {
        k_prop<<<prop_blocks, 256>>>(p_h, 128, p_z, 128, n);
        k_mma<<<dim3(mtiles, 4), 256, smem_sz>>>(p_z, 128, p_WTh + 512 * 128, p_WTl + 512 * 128,
                                                 128, p_base, nullptr,
                                                 out + (long long)tt * n * 128, n, 1);
    }
}

// round 7
// speedup vs baseline: 1.2864x; 1.0940x over previous
#include <cuda_runtime.h>
#include <cuda_bf16.h>
#include <math.h>
#include <stdint.h>

#define MAXN 20000
#define MAXE 320000

// ---------------- device scratch (no allocs allowed) ----------------
__device__ int   g_is64;
__device__ int   g_src[MAXE];
__device__ int   g_dst[MAXE];
__device__ int   g_esrc[MAXE];
__device__ float g_ewn[MAXE];
__device__ float g_deg[MAXN];
__device__ float g_dinv[MAXN];
__device__ int   g_cnt[MAXN];
__device__ int   g_rowptr[MAXN + 1];
__device__ int   g_cursor[MAXN];
__device__ int   g_part[32];
__device__ int   g_off2[32];
__device__ int   g_total;
__device__ float g_base[(long long)MAXN * 512];   // permuted gate layout
__device__ float g_h[MAXN * 128];
__device__ float g_c[MAXN * 128];
// bf16-split activations (A operands)
__device__ __nv_bfloat16 g_Ph[MAXN * 256];   // [P_h | P_c] hi
__device__ __nv_bfloat16 g_Pl[MAXN * 256];   // lo
__device__ __nv_bfloat16 g_zh[MAXN * 128];
__device__ __nv_bfloat16 g_zl[MAXN * 128];
// bf16-split transposed weights
// W_cell: [m in {0,1}][p = permuted col 0..511][k 0..127], perm p = t*128 + j*4 + q
__device__ __nv_bfloat16 g_WTh[2 * 512 * 128];
__device__ __nv_bfloat16 g_WTl[2 * 512 * 128];
// W_init: [p 0..255][k 0..255]
__device__ __nv_bfloat16 g_WIh[256 * 256];
__device__ __nv_bfloat16 g_WIl[256 * 256];

// ---------------- helpers ----------------
__device__ __forceinline__ float tanhA(float x) {
    float r; asm("tanh.approx.f32 %0, %1;" : "=f"(r) : "f"(x)); return r;
}
__device__ __forceinline__ float sigA(float x) {
    return fmaf(tanhA(0.5f * x), 0.5f, 0.5f);
}
__device__ __forceinline__ uint32_t smem_u32(const void* p) {
    uint32_t a;
    asm("{ .reg .u64 t; cvta.to.shared.u64 t, %1; cvt.u32.u64 %0, t; }" : "=r"(a) : "l"(p));
    return a;
}

#define CP16(dst, src, srcsz) \
    asm volatile("cp.async.ca.shared.global [%0], [%1], 16, %2;" \
        :: "r"(dst), "l"(src), "r"(srcsz))
#define CP_COMMIT() asm volatile("cp.async.commit_group;" ::: "memory")
#define CP_WAIT(nn) asm volatile("cp.async.wait_group %0;" :: "n"(nn) : "memory")

#define LDSM4(r0, r1, r2, r3, a) \
    asm volatile("ldmatrix.sync.aligned.m8n8.x4.shared.b16 {%0,%1,%2,%3}, [%4];" \
        : "=r"(r0), "=r"(r1), "=r"(r2), "=r"(r3) : "r"(a))

#define MMA16816(d, a0, a1, a2, a3, b0, b1) \
    asm volatile("mma.sync.aligned.m16n8k16.row.col.f32.bf16.bf16.f32 " \
        "{%0,%1,%2,%3}, {%4,%5,%6,%7}, {%8,%9}, {%0,%1,%2,%3};" \
        : "+f"((d)[0]), "+f"((d)[1]), "+f"((d)[2]), "+f"((d)[3]) \
        : "r"(a0), "r"(a1), "r"(a2), "r"(a3), "r"(b0), "r"(b1))

// smem swizzle: 64B rows, 4x16B granules, conflict-free for 8-row LDSM phases
__device__ __forceinline__ uint32_t swz(int row, int g) {
    return (uint32_t)(row * 64 + ((g ^ ((row >> 1) & 3)) << 4));
}

// ---------------- setup kernels ----------------
__global__ void k_init(int n) {
    int i = blockIdx.x * blockDim.x + threadIdx.x;
    if (i < n) { g_deg[i] = 0.f; g_cnt[i] = 0; }
    if (i == 0) g_is64 = 1;
}

__global__ void k_detect(const unsigned int* __restrict__ w) {
    unsigned int v = w[2 * threadIdx.x + 1];
    if (v != 0u) g_is64 = 0;
}

__global__ void k_build(const void* __restrict__ ei, const float* __restrict__ ea, int E) {
    int e = blockIdx.x * blockDim.x + threadIdx.x;
    if (e >= E) return;
    int s, d;
    if (g_is64) {
        const long long* p = (const long long*)ei;
        s = (int)p[e]; d = (int)p[E + e];
    } else {
        const int* p = (const int*)ei;
        s = p[e]; d = p[E + e];
    }
    g_src[e] = s; g_dst[e] = d;
    atomicAdd(&g_deg[d], ea[e]);
    atomicAdd(&g_cnt[d], 1);
}

// hierarchical scan pass 1 (+ dinv fused)
__global__ void k_scan1(int n) {
    __shared__ int s[1024];
    int i = blockIdx.x * 1024 + threadIdx.x;
    if (i < n) g_dinv[i] = rsqrtf(g_deg[i] + 1.0f);
    int v = (i < n) ? g_cnt[i] : 0;
    s[threadIdx.x] = v;
    __syncthreads();
    for (int off = 1; off < 1024; off <<= 1) {
        int t = (threadIdx.x >= off) ? s[threadIdx.x - off] : 0;
        __syncthreads();
        s[threadIdx.x] += t;
        __syncthreads();
    }
    if (i < n) g_rowptr[i] = s[threadIdx.x] - v;   // local exclusive
    if (threadIdx.x == 1023) g_part[blockIdx.x] = s[1023];
}

__global__ void k_scan2(int nb) {
    int tid = threadIdx.x;                 // 32 threads
    int v = (tid < nb) ? g_part[tid] : 0;
    int incl = v;
    for (int o = 1; o < 32; o <<= 1) {
        int t = __shfl_up_sync(0xffffffffu, incl, o);
        if (tid >= o) incl += t;
    }
    if (tid < nb) g_off2[tid] = incl - v;
    if (tid == 31) g_total = incl;
}

__global__ void k_scan3(int n) {
    int i = blockIdx.x * 1024 + threadIdx.x;
    if (i < n) {
        int val = g_rowptr[i] + g_off2[blockIdx.x];
        g_rowptr[i] = val;
        g_cursor[i] = val;
    }
    if (i == 0) g_rowptr[n] = g_total;
}

__global__ void k_scatter(const float* __restrict__ ea, int E) {
    int e = blockIdx.x * blockDim.x + threadIdx.x;
    if (e >= E) return;
    int s = g_src[e], d = g_dst[e];
    int pos = atomicAdd(&g_cursor[d], 1);
    g_esrc[pos] = s;
    g_ewn[pos] = g_dinv[s] * ea[e] * g_dinv[d];
}

// W_cell transpose + gate-interleave permute + bf16 split
// permuted p = t*128 + j*4 + q  <->  orig col q*128 + t*32 + j
__global__ void k_splitW(const float* __restrict__ Wc) {
    int id = blockIdx.x * blockDim.x + threadIdx.x;   // 0 .. 131071
    int m = id >> 16;
    int rem = id & 65535;
    int p = rem >> 7;
    int k = rem & 127;
    int t = p >> 7, r7 = p & 127;
    int j = r7 >> 2, q = r7 & 3;
    int nc = q * 128 + t * 32 + j;
    float v = Wc[(long long)(m * 128 + k) * 512 + nc];
    __nv_bfloat16 hb = __float2bfloat16_rn(v);
    float lf = v - __bfloat162float(hb);
    g_WTh[id] = hb;
    g_WTl[id] = __float2bfloat16_rn(lf);
}

// W_init transpose + bf16 split: [p][k] = Wi[k][p]
__global__ void k_splitWi(const float* __restrict__ Wi) {
    int id = blockIdx.x * blockDim.x + threadIdx.x;   // 0 .. 65535
    int p = id >> 8;
    int k = id & 255;
    float v = Wi[(long long)k * 256 + p];
    __nv_bfloat16 hb = __float2bfloat16_rn(v);
    float lf = v - __bfloat162float(hb);
    g_WIh[id] = hb;
    g_WIl[id] = __float2bfloat16_rn(lf);
}

// ---------------- sparse propagate -> bf16 hi/lo split output ----------------
__global__ void k_prop(const float* __restrict__ x, int ldx,
                       __nv_bfloat16* __restrict__ oh, __nv_bfloat16* __restrict__ ol,
                       int ldo, int n) {
    int v = (blockIdx.x * blockDim.x + threadIdx.x) >> 5;
    int lane = threadIdx.x & 31;
    if (v >= n) return;
    int beg = g_rowptr[v], end = g_rowptr[v + 1];
    float ax = 0.f, ay = 0.f, az = 0.f, aw = 0.f;
    int e = beg;
    for (; e + 1 < end; e += 2) {
        int s0 = g_esrc[e], s1 = g_esrc[e + 1];
        float w0 = g_ewn[e], w1 = g_ewn[e + 1];
        float4 v0 = __ldg((const float4*)(x + (long long)s0 * ldx) + lane);
        float4 v1 = __ldg((const float4*)(x + (long long)s1 * ldx) + lane);
        ax = fmaf(w0, v0.x, ax); ay = fmaf(w0, v0.y, ay);
        az = fmaf(w0, v0.z, az); aw = fmaf(w0, v0.w, aw);
        ax = fmaf(w1, v1.x, ax); ay = fmaf(w1, v1.y, ay);
        az = fmaf(w1, v1.z, az); aw = fmaf(w1, v1.w, aw);
    }
    if (e < end) {
        int s0 = g_esrc[e];
        float w0 = g_ewn[e];
        float4 v0 = __ldg((const float4*)(x + (long long)s0 * ldx) + lane);
        ax = fmaf(w0, v0.x, ax); ay = fmaf(w0, v0.y, ay);
        az = fmaf(w0, v0.z, az); aw = fmaf(w0, v0.w, aw);
    }
    float di = g_dinv[v];
    float w2 = di * di;
    float4 vv = __ldg((const float4*)(x + (long long)v * ldx) + lane);
    ax = fmaf(w2, vv.x, ax); ay = fmaf(w2, vv.y, ay);
    az = fmaf(w2, vv.z, az); aw = fmaf(w2, vv.w, aw);
    float a[4] = {ax, ay, az, aw};
    unsigned short hs[4], ls[4];
#pragma unroll
    for (int m = 0; m < 4; m++) {
        __nv_bfloat16 hb = __float2bfloat16_rn(a[m]);
        float lf = a[m] - __bfloat162float(hb);
        __nv_bfloat16 lb = __float2bfloat16_rn(lf);
        hs[m] = *(unsigned short*)&hb;
        ls[m] = *(unsigned short*)&lb;
    }
    *(uint2*)(oh + (long long)v * ldo + lane * 4) = *(uint2*)hs;
    *(uint2*)(ol + (long long)v * ldo + lane * 4) = *(uint2*)ls;
}

// ---------------- cp.async pipelined tensor-core GEMM (bf16 split-3) ----------------
// C[128 x 128] = A[m0:m0+128, :K] @ B[n0:n0+128, :K]^T, both bf16 hi/lo in gmem.
// smem per buf (32KB): Ah[0,8K) Al[8K,16K) Bh[16K,24K) Bl[24K,32K); 64B rows swizzled.
// mode 0: o512[r*512 + t*128 + c] = D + bc[orig col]   (permuted base precompute)
// mode 1: LSTM gates: D + base; update g_h/g_c; write oseq
// mode 2: init: elu(D + bi[col]) -> g_h (cols<128) / g_c
__global__ void __launch_bounds__(256, 2)
k_mma(const __nv_bfloat16* __restrict__ Ah, const __nv_bfloat16* __restrict__ Al, int lda,
      const __nv_bfloat16* __restrict__ Bh, const __nv_bfloat16* __restrict__ Bl,
      int K, const float* __restrict__ aux, float* __restrict__ o512,
      float* __restrict__ oseq, int n, int mode) {
    extern __shared__ char sm[];
    const uint32_t sb = smem_u32(sm);
    const int tid = threadIdx.x;
    const int lane = tid & 31;
    const int wid = tid >> 5;
    const int m0 = blockIdx.x * 128;
    const int t = blockIdx.y;
    const int mw = (wid & 3) * 32;
    const int nw = (wid >> 2) * 64;

    float acc[2][8][4];
#pragma unroll
    for (int i = 0; i < 2; i++)
#pragma unroll
        for (int j = 0; j < 8; j++)
#pragma unroll
            for (int q = 0; q < 4; q++) acc[i][j][q] = 0.f;

    const int nslab = K >> 5;

    // stage one 32-wide K slab via cp.async (8 granules per thread)
    auto stage = [&](int ks) {
        uint32_t bufo = (ks & 1) * 32768;
#pragma unroll
        for (int it = 0; it < 8; it++) {
            int id = tid + it * 256;          // 0..2047
            int arr = id >> 9;                // 0..3
            int rem = id & 511;
            int row = rem >> 2, g = rem & 3;
            uint32_t dst = sb + bufo + arr * 8192 + swz(row, g);
            if (arr < 2) {
                const __nv_bfloat16* src = (arr == 0 ? Ah : Al)
                    + (size_t)(m0 + row) * lda + ks * 32 + g * 8;
                int ok = (m0 + row < n) ? 16 : 0;
                CP16(dst, src, ok);
            } else {
                const __nv_bfloat16* src = (arr == 2 ? Bh : Bl)
                    + (size_t)(t * 128 + row) * K + ks * 32 + g * 8;
                CP16(dst, src, 16);
            }
        }
        CP_COMMIT();
    };

    stage(0);
    for (int ks = 0; ks < nslab; ks++) {
        if (ks + 1 < nslab) { stage(ks + 1); CP_WAIT(1); }
        else                { CP_WAIT(0); }
        __syncthreads();
        uint32_t abase = sb + (ks & 1) * 32768;
        uint32_t bbase = abase + 16384;
#pragma unroll
        for (int kc = 0; kc < 2; kc++) {
            uint32_t ah[2][4], al[2][4];
#pragma unroll
            for (int mf = 0; mf < 2; mf++) {
                int row = mw + mf * 16 + (lane & 15);
                int g = kc * 2 + (lane >> 4);
                uint32_t a = abase + swz(row, g);
                LDSM4(ah[mf][0], ah[mf][1], ah[mf][2], ah[mf][3], a);
                LDSM4(al[mf][0], al[mf][1], al[mf][2], al[mf][3], a + 8192);
            }
#pragma unroll
            for (int bp = 0; bp < 4; bp++) {
                int p = nw + bp * 16 + ((lane >> 4) << 3) + (lane & 7);
                int g = kc * 2 + ((lane >> 3) & 1);
                uint32_t a = bbase + swz(p, g);
                uint32_t h0, h1, h2, h3, l0, l1, l2, l3;
                LDSM4(h0, h1, h2, h3, a);
                LDSM4(l0, l1, l2, l3, a + 8192);
                // term-major: accumulator reuse distance = 4
                MMA16816(acc[0][2 * bp],     ah[0][0], ah[0][1], ah[0][2], ah[0][3], h0, h1);
                MMA16816(acc[1][2 * bp],     ah[1][0], ah[1][1], ah[1][2], ah[1][3], h0, h1);
                MMA16816(acc[0][2 * bp + 1], ah[0][0], ah[0][1], ah[0][2], ah[0][3], h2, h3);
                MMA16816(acc[1][2 * bp + 1], ah[1][0], ah[1][1], ah[1][2], ah[1][3], h2, h3);
                MMA16816(acc[0][2 * bp],     ah[0][0], ah[0][1], ah[0][2], ah[0][3], l0, l1);
                MMA16816(acc[1][2 * bp],     ah[1][0], ah[1][1], ah[1][2], ah[1][3], l0, l1);
                MMA16816(acc[0][2 * bp + 1], ah[0][0], ah[0][1], ah[0][2], ah[0][3], l2, l3);
                MMA16816(acc[1][2 * bp + 1], ah[1][0], ah[1][1], ah[1][2], ah[1][3], l2, l3);
                MMA16816(acc[0][2 * bp],     al[0][0], al[0][1], al[0][2], al[0][3], h0, h1);
                MMA16816(acc[1][2 * bp],     al[1][0], al[1][1], al[1][2], al[1][3], h0, h1);
                MMA16816(acc[0][2 * bp + 1], al[0][0], al[0][1], al[0][2], al[0][3], h2, h3);
                MMA16816(acc[1][2 * bp + 1], al[1][0], al[1][1], al[1][2], al[1][3], h2, h3);
            }
        }
        __syncthreads();
    }

    // ---- epilogue ----
#pragma unroll
    for (int mf = 0; mf < 2; mf++) {
        int r0 = m0 + mw + mf * 16 + (lane >> 2);
        int r1 = r0 + 8;
#pragma unroll
        for (int nf = 0; nf < 8; nf++) {
            float d0 = acc[mf][nf][0], d1 = acc[mf][nf][1];
            float d2 = acc[mf][nf][2], d3 = acc[mf][nf][3];
            int c0 = nw + nf * 8 + (lane & 3) * 2;
            if (mode == 2) {
                int gc = t * 128 + c0;
                float2 bb = *(const float2*)(aux + gc);
                float* dst = (gc < 128) ? (g_h + gc) : (g_c + gc - 128);
                if (r0 < n) {
                    float e0 = d0 + bb.x, e1 = d1 + bb.y;
                    e0 = (e0 > 0.f) ? e0 : expm1f(e0);
                    e1 = (e1 > 0.f) ? e1 : expm1f(e1);
                    float2 o; o.x = e0; o.y = e1;
                    *(float2*)(dst + (size_t)r0 * 128) = o;
                }
                if (r1 < n) {
                    float e0 = d2 + bb.x, e1 = d3 + bb.y;
                    e0 = (e0 > 0.f) ? e0 : expm1f(e0);
                    e1 = (e1 > 0.f) ? e1 : expm1f(e1);
                    float2 o; o.x = e0; o.y = e1;
                    *(float2*)(dst + (size_t)r1 * 128) = o;
                }
            } else if (mode == 0) {
                int j = c0 >> 2, q = c0 & 3;
                float bb0 = aux[q * 128 + t * 32 + j];
                float bb1 = aux[(q + 1) * 128 + t * 32 + j];
                if (r0 < n) {
                    float2 o; o.x = d0 + bb0; o.y = d1 + bb1;
                    *(float2*)(o512 + (size_t)r0 * 512 + t * 128 + c0) = o;
                }
                if (r1 < n) {
                    float2 o; o.x = d2 + bb0; o.y = d3 + bb1;
                    *(float2*)(o512 + (size_t)r1 * 512 + t * 128 + c0) = o;
                }
            } else {
                float2 b0 = make_float2(0.f, 0.f), b1 = make_float2(0.f, 0.f);
                if (r0 < n) b0 = *(const float2*)(aux + (size_t)r0 * 512 + t * 128 + c0);
                if (r1 < n) b1 = *(const float2*)(aux + (size_t)r1 * 512 + t * 128 + c0);
                float v0 = d0 + b0.x, v1 = d1 + b0.y;
                float v2 = d2 + b1.x, v3 = d3 + b1.y;
                float u0 = __shfl_xor_sync(0xffffffffu, v0, 1);
                float u1 = __shfl_xor_sync(0xffffffffu, v1, 1);
                float u2 = __shfl_xor_sync(0xffffffffu, v2, 1);
                float u3 = __shfl_xor_sync(0xffffffffu, v3, 1);
                if (!(lane & 1)) {
                    // this lane: (i, f); partner: (o, g)
                    int j = c0 >> 2;
                    int hcol = t * 32 + j;
                    if (r0 < n) {
                        size_t ix = (size_t)r0 * 128 + hcol;
                        float cold = g_c[ix];
                        float cn = sigA(v1) * cold + sigA(v0) * tanhA(u1);
                        float hn = sigA(u0) * tanhA(cn);
                        g_c[ix] = cn; g_h[ix] = hn; oseq[ix] = hn;
                    }
                    if (r1 < n) {
                        size_t ix = (size_t)r1 * 128 + hcol;
                        float cold = g_c[ix];
                        float cn = sigA(v3) * cold + sigA(v2) * tanhA(u3);
                        float hn = sigA(u2) * tanhA(cn);
                        g_c[ix] = cn; g_h[ix] = hn; oseq[ix] = hn;
                    }
                }
            }
        }
    }
}

// ---------------- host launcher ----------------
extern "C" void kernel_launch(void* const* d_in, const int* in_sizes, int n_in,
                              void* d_out, int out_size) {
    const float* h  = (const float*)d_in[0];
    const float* c  = (const float*)d_in[1];
    const void*  ei = d_in[2];
    const float* ea = (const float*)d_in[3];
    const float* Wi = (const float*)d_in[4];
    const float* bi = (const float*)d_in[5];
    const float* Wc = (const float*)d_in[6];
    const float* bc = (const float*)d_in[7];
    float* out = (float*)d_out;

    int n   = in_sizes[0] / 128;
    int E   = in_sizes[3];
    int seq = out_size / (n * 128);

    static float* p_base = nullptr;
    static float* p_h = nullptr;
    static __nv_bfloat16 *p_Ph, *p_Pl, *p_zh, *p_zl, *p_WTh, *p_WTl, *p_WIh, *p_WIl;
    if (!p_base) {
        cudaGetSymbolAddress((void**)&p_base, g_base);
        cudaGetSymbolAddress((void**)&p_h, g_h);
        cudaGetSymbolAddress((void**)&p_Ph, g_Ph);
        cudaGetSymbolAddress((void**)&p_Pl, g_Pl);
        cudaGetSymbolAddress((void**)&p_zh, g_zh);
        cudaGetSymbolAddress((void**)&p_zl, g_zl);
        cudaGetSymbolAddress((void**)&p_WTh, g_WTh);
        cudaGetSymbolAddress((void**)&p_WTl, g_WTl);
        cudaGetSymbolAddress((void**)&p_WIh, g_WIh);
        cudaGetSymbolAddress((void**)&p_WIl, g_WIl);
        cudaFuncSetAttribute(k_mma, cudaFuncAttributeMaxDynamicSharedMemorySize, 65536);
    }

    int nb256 = (n + 255) / 256;
    int eb256 = (E + 255) / 256;
    int nb1024 = (n + 1023) / 1024;
    int mtiles = (n + 127) / 128;
    int prop_blocks = (n * 32 + 255) / 256;
    size_t smem_sz = 65536;

    // ---- graph setup (per launch; deterministic) ----
    k_init<<<nb256, 256>>>(n);
    k_detect<<<1, 128>>>((const unsigned int*)ei);
    k_build<<<eb256, 256>>>(ei, ea, E);
    k_scan1<<<nb1024, 1024>>>(n);        // also computes dinv
    k_scan2<<<1, 32>>>(nb1024);
    k_scan3<<<nb1024, 1024>>>(n);
    k_scatter<<<eb256, 256>>>(ea, E);
    k_splitW<<<512, 256>>>(Wc);
    k_splitWi<<<256, 256>>>(Wi);

    // ---- loop-invariant precompute ----
    k_prop<<<prop_blocks, 256>>>(h, 128, p_Ph, p_Pl, 256, n);          // P_h split
    k_prop<<<prop_blocks, 256>>>(c, 128, p_Ph + 128, p_Pl + 128, 256, n); // P_c split
    // init: elu(Phc @ W_init + b_init) -> g_h, g_c
    k_mma<<<dim3(mtiles, 2), 256, smem_sz>>>(p_Ph, p_Pl, 256, p_WIh, p_WIl, 256,
                                             bi, nullptr, nullptr, n, 2);
    // base_perm = P_h @ Wc[0:128] + b_cell
    k_mma<<<dim3(mtiles, 4), 256, smem_sz>>>(p_Ph, p_Pl, 256, p_WTh, p_WTl, 128,
                                             bc, p_base, nullptr, n, 0);

    // ---- sequence ----
    for (int tt = 0; tt < seq; tt++) {
        k_prop<<<prop_blocks, 256>>>(p_h, 128, p_zh, p_zl, 128, n);
        k_mma<<<dim3(mtiles, 4), 256, smem_sz>>>(p_zh, p_zl, 128,
                                                 p_WTh + 512 * 128, p_WTl + 512 * 128, 128,
                                                 p_base, nullptr,
                                                 out + (long long)tt * n * 128, n, 1);
    }
}

// round 8
// speedup vs baseline: 1.3098x; 1.0181x over previous
#include <cuda_runtime.h>
#include <cuda_bf16.h>
#include <math.h>
#include <stdint.h>

#define MAXN 20000
#define MAXE 320000

// ---------------- device scratch (no allocs allowed) ----------------
__device__ int   g_is64;
__device__ int   g_src[MAXE];
__device__ int   g_dst[MAXE];
__device__ int   g_esrc[MAXE];
__device__ float g_ewn[MAXE];
__device__ float g_deg[MAXN];
__device__ float g_dinv[MAXN];
__device__ int   g_cnt[MAXN];
__device__ int   g_rowptr[MAXN + 1];
__device__ int   g_cursor[MAXN];
__device__ int   g_part[32];
__device__ int   g_off2[32];
__device__ int   g_total;
__device__ float g_base[(long long)MAXN * 512];   // permuted gate layout
__device__ float g_h[MAXN * 128];
__device__ float g_c[MAXN * 128];
// bf16-split activations (A operands)
__device__ __nv_bfloat16 g_Ph[MAXN * 256];   // [P_h | P_c] hi
__device__ __nv_bfloat16 g_Pl[MAXN * 256];   // lo
__device__ __nv_bfloat16 g_zh[MAXN * 128];
__device__ __nv_bfloat16 g_zl[MAXN * 128];
// bf16-split transposed weights
// W_cell: [m in {0,1}][p = permuted col 0..511][k 0..127], perm p = t*128 + j*4 + q
__device__ __nv_bfloat16 g_WTh[2 * 512 * 128];
__device__ __nv_bfloat16 g_WTl[2 * 512 * 128];
// W_init: [p 0..255][k 0..255]
__device__ __nv_bfloat16 g_WIh[256 * 256];
__device__ __nv_bfloat16 g_WIl[256 * 256];

// ---------------- helpers ----------------
__device__ __forceinline__ float tanhA(float x) {
    float r; asm("tanh.approx.f32 %0, %1;" : "=f"(r) : "f"(x)); return r;
}
__device__ __forceinline__ float sigA(float x) {
    return fmaf(tanhA(0.5f * x), 0.5f, 0.5f);
}
__device__ __forceinline__ uint32_t smem_u32(const void* p) {
    uint32_t a;
    asm("{ .reg .u64 t; cvta.to.shared.u64 t, %1; cvt.u32.u64 %0, t; }" : "=r"(a) : "l"(p));
    return a;
}

#define CP16(dst, src, srcsz) \
    asm volatile("cp.async.ca.shared.global [%0], [%1], 16, %2;" \
        :: "r"(dst), "l"(src), "r"(srcsz))
#define CP_COMMIT() asm volatile("cp.async.commit_group;" ::: "memory")
#define CP_WAIT(nn) asm volatile("cp.async.wait_group %0;" :: "n"(nn) : "memory")

#define LDSM4(r0, r1, r2, r3, a) \
    asm volatile("ldmatrix.sync.aligned.m8n8.x4.shared.b16 {%0,%1,%2,%3}, [%4];" \
        : "=r"(r0), "=r"(r1), "=r"(r2), "=r"(r3) : "r"(a))

#define MMA16816(d, a0, a1, a2, a3, b0, b1) \
    asm volatile("mma.sync.aligned.m16n8k16.row.col.f32.bf16.bf16.f32 " \
        "{%0,%1,%2,%3}, {%4,%5,%6,%7}, {%8,%9}, {%0,%1,%2,%3};" \
        : "+f"((d)[0]), "+f"((d)[1]), "+f"((d)[2]), "+f"((d)[3]) \
        : "r"(a0), "r"(a1), "r"(a2), "r"(a3), "r"(b0), "r"(b1))

// smem swizzle: 64B rows, 4x16B granules, conflict-free for 8-row LDSM phases
__device__ __forceinline__ uint32_t swz(int row, int g) {
    return (uint32_t)(row * 64 + ((g ^ ((row >> 1) & 3)) << 4));
}

// ---------------- setup kernels ----------------
__global__ void k_init(int n) {
    int i = blockIdx.x * blockDim.x + threadIdx.x;
    if (i < n) { g_deg[i] = 0.f; g_cnt[i] = 0; }
    if (i == 0) g_is64 = 1;
}

__global__ void k_detect(const unsigned int* __restrict__ w) {
    unsigned int v = w[2 * threadIdx.x + 1];
    if (v != 0u) g_is64 = 0;
}

__global__ void k_build(const void* __restrict__ ei, const float* __restrict__ ea, int E) {
    int e = blockIdx.x * blockDim.x + threadIdx.x;
    if (e >= E) return;
    int s, d;
    if (g_is64) {
        const long long* p = (const long long*)ei;
        s = (int)p[e]; d = (int)p[E + e];
    } else {
        const int* p = (const int*)ei;
        s = p[e]; d = p[E + e];
    }
    g_src[e] = s; g_dst[e] = d;
    atomicAdd(&g_deg[d], ea[e]);
    atomicAdd(&g_cnt[d], 1);
}

// hierarchical scan pass 1 (+ dinv fused)
__global__ void k_scan1(int n) {
    __shared__ int s[1024];
    int i = blockIdx.x * 1024 + threadIdx.x;
    if (i < n) g_dinv[i] = rsqrtf(g_deg[i] + 1.0f);
    int v = (i < n) ? g_cnt[i] : 0;
    s[threadIdx.x] = v;
    __syncthreads();
    for (int off = 1; off < 1024; off <<= 1) {
        int t = (threadIdx.x >= off) ? s[threadIdx.x - off] : 0;
        __syncthreads();
        s[threadIdx.x] += t;
        __syncthreads();
    }
    if (i < n) g_rowptr[i] = s[threadIdx.x] - v;   // local exclusive
    if (threadIdx.x == 1023) g_part[blockIdx.x] = s[1023];
}

__global__ void k_scan2(int nb) {
    int tid = threadIdx.x;                 // 32 threads
    int v = (tid < nb) ? g_part[tid] : 0;
    int incl = v;
    for (int o = 1; o < 32; o <<= 1) {
        int t = __shfl_up_sync(0xffffffffu, incl, o);
        if (tid >= o) incl += t;
    }
    if (tid < nb) g_off2[tid] = incl - v;
    if (tid == 31) g_total = incl;
}

__global__ void k_scan3(int n) {
    int i = blockIdx.x * 1024 + threadIdx.x;
    if (i < n) {
        int val = g_rowptr[i] + g_off2[blockIdx.x];
        g_rowptr[i] = val;
        g_cursor[i] = val;
    }
    if (i == 0) g_rowptr[n] = g_total;
}

__global__ void k_scatter(const float* __restrict__ ea, int E) {
    int e = blockIdx.x * blockDim.x + threadIdx.x;
    if (e >= E) return;
    int s = g_src[e], d = g_dst[e];
    int pos = atomicAdd(&g_cursor[d], 1);
    g_esrc[pos] = s;
    g_ewn[pos] = g_dinv[s] * ea[e] * g_dinv[d];
}

// fused weight transpose + permute + bf16 split (W_cell and W_init)
// ids [0, 131072): W_cell  perm p = t*128 + j*4 + q  <->  orig col q*128 + t*32 + j
// ids [131072, 196608): W_init transposed [p][k] = Wi[k][p]
__global__ void k_split(const float* __restrict__ Wc, const float* __restrict__ Wi) {
    int id = blockIdx.x * blockDim.x + threadIdx.x;   // 0 .. 196607
    if (id < 131072) {
        int m = id >> 16;
        int rem = id & 65535;
        int p = rem >> 7;
        int k = rem & 127;
        int t = p >> 7, r7 = p & 127;
        int j = r7 >> 2, q = r7 & 3;
        int nc = q * 128 + t * 32 + j;
        float v = Wc[(long long)(m * 128 + k) * 512 + nc];
        __nv_bfloat16 hb = __float2bfloat16_rn(v);
        float lf = v - __bfloat162float(hb);
        g_WTh[id] = hb;
        g_WTl[id] = __float2bfloat16_rn(lf);
    } else {
        int id2 = id - 131072;
        int p = id2 >> 8;
        int k = id2 & 255;
        float v = Wi[(long long)k * 256 + p];
        __nv_bfloat16 hb = __float2bfloat16_rn(v);
        float lf = v - __bfloat162float(hb);
        g_WIh[id2] = hb;
        g_WIl[id2] = __float2bfloat16_rn(lf);
    }
}

// ---------------- sparse propagate -> bf16 hi/lo split output ----------------
// grid.y selects input (x0 or x1); output col offset = blockIdx.y*128, stride ldo.
__global__ void k_prop(const float* __restrict__ x0, const float* __restrict__ x1,
                       __nv_bfloat16* __restrict__ oh, __nv_bfloat16* __restrict__ ol,
                       int ldo, int n) {
    const float* x = blockIdx.y ? x1 : x0;
    int coff = blockIdx.y * 128;
    int v = (blockIdx.x * blockDim.x + threadIdx.x) >> 5;
    int lane = threadIdx.x & 31;
    if (v >= n) return;
    int beg = g_rowptr[v], end = g_rowptr[v + 1];
    float ax = 0.f, ay = 0.f, az = 0.f, aw = 0.f;
    int e = beg;
    for (; e + 1 < end; e += 2) {
        int s0 = g_esrc[e], s1 = g_esrc[e + 1];
        float w0 = g_ewn[e], w1 = g_ewn[e + 1];
        float4 v0 = __ldg((const float4*)(x + (long long)s0 * 128) + lane);
        float4 v1 = __ldg((const float4*)(x + (long long)s1 * 128) + lane);
        ax = fmaf(w0, v0.x, ax); ay = fmaf(w0, v0.y, ay);
        az = fmaf(w0, v0.z, az); aw = fmaf(w0, v0.w, aw);
        ax = fmaf(w1, v1.x, ax); ay = fmaf(w1, v1.y, ay);
        az = fmaf(w1, v1.z, az); aw = fmaf(w1, v1.w, aw);
    }
    if (e < end) {
        int s0 = g_esrc[e];
        float w0 = g_ewn[e];
        float4 v0 = __ldg((const float4*)(x + (long long)s0 * 128) + lane);
        ax = fmaf(w0, v0.x, ax); ay = fmaf(w0, v0.y, ay);
        az = fmaf(w0, v0.z, az); aw = fmaf(w0, v0.w, aw);
    }
    float di = g_dinv[v];
    float w2 = di * di;
    float4 vv = __ldg((const float4*)(x + (long long)v * 128) + lane);
    ax = fmaf(w2, vv.x, ax); ay = fmaf(w2, vv.y, ay);
    az = fmaf(w2, vv.z, az); aw = fmaf(w2, vv.w, aw);
    float a[4] = {ax, ay, az, aw};
    unsigned short hs[4], ls[4];
#pragma unroll
    for (int m = 0; m < 4; m++) {
        __nv_bfloat16 hb = __float2bfloat16_rn(a[m]);
        float lf = a[m] - __bfloat162float(hb);
        __nv_bfloat16 lb = __float2bfloat16_rn(lf);
        hs[m] = *(unsigned short*)&hb;
        ls[m] = *(unsigned short*)&lb;
    }
    *(uint2*)(oh + (long long)v * ldo + coff + lane * 4) = *(uint2*)hs;
    *(uint2*)(ol + (long long)v * ldo + coff + lane * 4) = *(uint2*)ls;
}

// ---------------- 3-stage cp.async pipelined tensor-core GEMM (bf16 split-3) ----------------
// C[128 x 128] = A[m0:m0+128, :K] @ B[n0:n0+128, :K]^T, both bf16 hi/lo in gmem.
// smem: 3 bufs x 32KB: Ah[0,8K) Al[8K,16K) Bh[16K,24K) Bl[24K,32K); 64B swizzled rows.
// mode 0: o512[r*512 + t*128 + c] = D + bc[orig col]   (permuted base precompute)
// mode 1: LSTM gates: D + base; update g_c; write oseq (h lives in oseq)
// mode 2: init: elu(D + bi[col]) -> g_h (cols<128) / g_c
__global__ void __launch_bounds__(256, 2)
k_mma(const __nv_bfloat16* __restrict__ Ah, const __nv_bfloat16* __restrict__ Al, int lda,
      const __nv_bfloat16* __restrict__ Bh, const __nv_bfloat16* __restrict__ Bl,
      int K, const float* __restrict__ aux, float* __restrict__ o512,
      float* __restrict__ oseq, int n, int mode) {
    extern __shared__ char sm[];
    const uint32_t sb = smem_u32(sm);
    const int tid = threadIdx.x;
    const int lane = tid & 31;
    const int wid = tid >> 5;
    const int m0 = blockIdx.x * 128;
    const int t = blockIdx.y;
    const int mw = (wid & 3) * 32;
    const int nw = (wid >> 2) * 64;

    float acc[2][8][4];
#pragma unroll
    for (int i = 0; i < 2; i++)
#pragma unroll
        for (int j = 0; j < 8; j++)
#pragma unroll
            for (int q = 0; q < 4; q++) acc[i][j][q] = 0.f;

    const int nslab = K >> 5;

    auto stage = [&](int ks) {
        uint32_t bufo = (uint32_t)(ks % 3) * 32768;
#pragma unroll
        for (int it = 0; it < 8; it++) {
            int id = tid + it * 256;          // 0..2047
            int arr = id >> 9;                // 0..3
            int rem = id & 511;
            int row = rem >> 2, g = rem & 3;
            uint32_t dst = sb + bufo + arr * 8192 + swz(row, g);
            if (arr < 2) {
                const __nv_bfloat16* src = (arr == 0 ? Ah : Al)
                    + (size_t)(m0 + row) * lda + ks * 32 + g * 8;
                int ok = (m0 + row < n) ? 16 : 0;
                CP16(dst, src, ok);
            } else {
                const __nv_bfloat16* src = (arr == 2 ? Bh : Bl)
                    + (size_t)(t * 128 + row) * K + ks * 32 + g * 8;
                CP16(dst, src, 16);
            }
        }
        CP_COMMIT();
    };

    stage(0);
    stage(1);
    for (int ks = 0; ks < nslab; ks++) {
        if (ks == nslab - 1) { CP_WAIT(0); } else { CP_WAIT(1); }
        __syncthreads();
        if (ks + 2 < nslab) stage(ks + 2);
        uint32_t abase = sb + (uint32_t)(ks % 3) * 32768;
        uint32_t bbase = abase + 16384;
#pragma unroll
        for (int kc = 0; kc < 2; kc++) {
            uint32_t ah[2][4], al[2][4];
#pragma unroll
            for (int mf = 0; mf < 2; mf++) {
                int row = mw + mf * 16 + (lane & 15);
                int g = kc * 2 + (lane >> 4);
                uint32_t a = abase + swz(row, g);
                LDSM4(ah[mf][0], ah[mf][1], ah[mf][2], ah[mf][3], a);
                LDSM4(al[mf][0], al[mf][1], al[mf][2], al[mf][3], a + 8192);
            }
#pragma unroll
            for (int bp = 0; bp < 4; bp++) {
                int p = nw + bp * 16 + ((lane >> 4) << 3) + (lane & 7);
                int g = kc * 2 + ((lane >> 3) & 1);
                uint32_t a = bbase + swz(p, g);
                uint32_t h0, h1, h2, h3, l0, l1, l2, l3;
                LDSM4(h0, h1, h2, h3, a);
                LDSM4(l0, l1, l2, l3, a + 8192);
                // term-major: accumulator reuse distance = 4
                MMA16816(acc[0][2 * bp],     ah[0][0], ah[0][1], ah[0][2], ah[0][3], h0, h1);
                MMA16816(acc[1][2 * bp],     ah[1][0], ah[1][1], ah[1][2], ah[1][3], h0, h1);
                MMA16816(acc[0][2 * bp + 1], ah[0][0], ah[0][1], ah[0][2], ah[0][3], h2, h3);
                MMA16816(acc[1][2 * bp + 1], ah[1][0], ah[1][1], ah[1][2], ah[1][3], h2, h3);
                MMA16816(acc[0][2 * bp],     ah[0][0], ah[0][1], ah[0][2], ah[0][3], l0, l1);
                MMA16816(acc[1][2 * bp],     ah[1][0], ah[1][1], ah[1][2], ah[1][3], l0, l1);
                MMA16816(acc[0][2 * bp + 1], ah[0][0], ah[0][1], ah[0][2], ah[0][3], l2, l3);
                MMA16816(acc[1][2 * bp + 1], ah[1][0], ah[1][1], ah[1][2], ah[1][3], l2, l3);
                MMA16816(acc[0][2 * bp],     al[0][0], al[0][1], al[0][2], al[0][3], h0, h1);
                MMA16816(acc[1][2 * bp],     al[1][0], al[1][1], al[1][2], al[1][3], h0, h1);
                MMA16816(acc[0][2 * bp + 1], al[0][0], al[0][1], al[0][2], al[0][3], h2, h3);
                MMA16816(acc[1][2 * bp + 1], al[1][0], al[1][1], al[1][2], al[1][3], h2, h3);
            }
        }
    }

    // ---- epilogue ----
#pragma unroll
    for (int mf = 0; mf < 2; mf++) {
        int r0 = m0 + mw + mf * 16 + (lane >> 2);
        int r1 = r0 + 8;
#pragma unroll
        for (int nf = 0; nf < 8; nf++) {
            float d0 = acc[mf][nf][0], d1 = acc[mf][nf][1];
            float d2 = acc[mf][nf][2], d3 = acc[mf][nf][3];
            int c0 = nw + nf * 8 + (lane & 3) * 2;
            if (mode == 2) {
                int gc = t * 128 + c0;
                float2 bb = *(const float2*)(aux + gc);
                float* dst = (gc < 128) ? (g_h + gc) : (g_c + gc - 128);
                if (r0 < n) {
                    float e0 = d0 + bb.x, e1 = d1 + bb.y;
                    e0 = (e0 > 0.f) ? e0 : expm1f(e0);
                    e1 = (e1 > 0.f) ? e1 : expm1f(e1);
                    float2 o; o.x = e0; o.y = e1;
                    *(float2*)(dst + (size_t)r0 * 128) = o;
                }
                if (r1 < n) {
                    float e0 = d2 + bb.x, e1 = d3 + bb.y;
                    e0 = (e0 > 0.f) ? e0 : expm1f(e0);
                    e1 = (e1 > 0.f) ? e1 : expm1f(e1);
                    float2 o; o.x = e0; o.y = e1;
                    *(float2*)(dst + (size_t)r1 * 128) = o;
                }
            } else if (mode == 0) {
                int j = c0 >> 2, q = c0 & 3;
                float bb0 = aux[q * 128 + t * 32 + j];
                float bb1 = aux[(q + 1) * 128 + t * 32 + j];
                if (r0 < n) {
                    float2 o; o.x = d0 + bb0; o.y = d1 + bb1;
                    *(float2*)(o512 + (size_t)r0 * 512 + t * 128 + c0) = o;
                }
                if (r1 < n) {
                    float2 o; o.x = d2 + bb0; o.y = d3 + bb1;
                    *(float2*)(o512 + (size_t)r1 * 512 + t * 128 + c0) = o;
                }
            } else {
                float2 b0 = make_float2(0.f, 0.f), b1 = make_float2(0.f, 0.f);
                if (r0 < n) b0 = *(const float2*)(aux + (size_t)r0 * 512 + t * 128 + c0);
                if (r1 < n) b1 = *(const float2*)(aux + (size_t)r1 * 512 + t * 128 + c0);
                float v0 = d0 + b0.x, v1 = d1 + b0.y;
                float v2 = d2 + b1.x, v3 = d3 + b1.y;
                float u0 = __shfl_xor_sync(0xffffffffu, v0, 1);
                float u1 = __shfl_xor_sync(0xffffffffu, v1, 1);
                float u2 = __shfl_xor_sync(0xffffffffu, v2, 1);
                float u3 = __shfl_xor_sync(0xffffffffu, v3, 1);
                if (!(lane & 1)) {
                    // this lane: (i, f); partner: (o, g)
                    int j = c0 >> 2;
                    int hcol = t * 32 + j;
                    if (r0 < n) {
                        size_t ix = (size_t)r0 * 128 + hcol;
                        float cold = g_c[ix];
                        float cn = sigA(v1) * cold + sigA(v0) * tanhA(u1);
                        float hn = sigA(u0) * tanhA(cn);
                        g_c[ix] = cn; oseq[ix] = hn;
                    }
                    if (r1 < n) {
                        size_t ix = (size_t)r1 * 128 + hcol;
                        float cold = g_c[ix];
                        float cn = sigA(v3) * cold + sigA(v2) * tanhA(u3);
                        float hn = sigA(u2) * tanhA(cn);
                        g_c[ix] = cn; oseq[ix] = hn;
                    }
                }
            }
        }
    }
}

// ---------------- host launcher ----------------
extern "C" void kernel_launch(void* const* d_in, const int* in_sizes, int n_in,
                              void* d_out, int out_size) {
    const float* h  = (const float*)d_in[0];
    const float* c  = (const float*)d_in[1];
    const void*  ei = d_in[2];
    const float* ea = (const float*)d_in[3];
    const float* Wi = (const float*)d_in[4];
    const float* bi = (const float*)d_in[5];
    const float* Wc = (const float*)d_in[6];
    const float* bc = (const float*)d_in[7];
    float* out = (float*)d_out;

    int n   = in_sizes[0] / 128;
    int E   = in_sizes[3];
    int seq = out_size / (n * 128);

    static float* p_base = nullptr;
    static float* p_h = nullptr;
    static __nv_bfloat16 *p_Ph, *p_Pl, *p_zh, *p_zl, *p_WTh, *p_WTl, *p_WIh, *p_WIl;
    if (!p_base) {
        cudaGetSymbolAddress((void**)&p_base, g_base);
        cudaGetSymbolAddress((void**)&p_h, g_h);
        cudaGetSymbolAddress((void**)&p_Ph, g_Ph);
        cudaGetSymbolAddress((void**)&p_Pl, g_Pl);
        cudaGetSymbolAddress((void**)&p_zh, g_zh);
        cudaGetSymbolAddress((void**)&p_zl, g_zl);
        cudaGetSymbolAddress((void**)&p_WTh, g_WTh);
        cudaGetSymbolAddress((void**)&p_WTl, g_WTl);
        cudaGetSymbolAddress((void**)&p_WIh, g_WIh);
        cudaGetSymbolAddress((void**)&p_WIl, g_WIl);
        cudaFuncSetAttribute(k_mma, cudaFuncAttributeMaxDynamicSharedMemorySize, 98304);
    }

    int nb256 = (n + 255) / 256;
    int eb256 = (E + 255) / 256;
    int nb1024 = (n + 1023) / 1024;
    int mtiles = (n + 127) / 128;
    int prop_blocks = (n * 32 + 255) / 256;
    size_t smem_sz = 98304;

    // ---- graph setup (per launch; deterministic) ----
    k_init<<<nb256, 256>>>(n);
    k_detect<<<1, 128>>>((const unsigned int*)ei);
    k_build<<<eb256, 256>>>(ei, ea, E);
    k_scan1<<<nb1024, 1024>>>(n);        // also computes dinv
    k_scan2<<<1, 32>>>(nb1024);
    k_scan3<<<nb1024, 1024>>>(n);
    k_scatter<<<eb256, 256>>>(ea, E);
    k_split<<<768, 256>>>(Wc, Wi);

    // ---- loop-invariant precompute ----
    // fused P_h | P_c propagate (grid.y = 2)
    k_prop<<<dim3(prop_blocks, 2), 256>>>(h, c, p_Ph, p_Pl, 256, n);
    // init: elu(Phc @ W_init + b_init) -> g_h, g_c
    k_mma<<<dim3(mtiles, 2), 256, smem_sz>>>(p_Ph, p_Pl, 256, p_WIh, p_WIl, 256,
                                             bi, nullptr, nullptr, n, 2);
    // base_perm = P_h @ Wc[0:128] + b_cell
    k_mma<<<dim3(mtiles, 4), 256, smem_sz>>>(p_Ph, p_Pl, 256, p_WTh, p_WTl, 128,
                                             bc, p_base, nullptr, n, 0);

    // ---- sequence: h(t) lives in out[t-1] slab ----
    const float* hsrc = p_h;
    for (int tt = 0; tt < seq; tt++) {
        k_prop<<<dim3(prop_blocks, 1), 256>>>(hsrc, nullptr, p_zh, p_zl, 128, n);
        float* odst = out + (long long)tt * n * 128;
        k_mma<<<dim3(mtiles, 4), 256, smem_sz>>>(p_zh, p_zl, 128,
                                                 p_WTh + 512 * 128, p_WTl + 512 * 128, 128,
                                                 p_base, nullptr, odst, n, 1);
        hsrc = odst;
    }
}